// round 6
// baseline (speedup 1.0000x reference)
#include <cuda_runtime.h>

#define NVOX 65536
#define CCH  64
#define NHEAD 4
#define HD   16
#define KVOL 125
#define NPAIR 1048576

// Scratch (static device globals per harness rules)
__device__ __align__(16) float g_nq[NVOX * CCH];
__device__ __align__(16) float g_nk[NVOX * CCH];
__device__ __align__(16) float g_v [NVOX * CCH];
__device__ __align__(16) float g_agg[NVOX * CCH];
__device__ __align__(16) float g_npos[KVOL * CCH];

// CSR build scratch
__device__ __align__(16) int      g_cnt[NVOX];
__device__ __align__(16) int      g_off[NVOX + 1];
__device__ __align__(16) int      g_bsum[256];
__device__ __align__(16) unsigned g_pi0[NPAIR];   // packed in_idx*125+kid, sorted by out

// ---------------------------------------------------------------------------
// f32x2 packed-FMA helpers (sm_10x: FFMA2 only reachable via PTX)
// ---------------------------------------------------------------------------
__device__ __forceinline__ unsigned long long pack2(float a) {
    unsigned long long r;
    asm("mov.b64 %0, {%1, %1};" : "=l"(r) : "f"(a));
    return r;
}
__device__ __forceinline__ void fma2(unsigned long long& d,
                                     unsigned long long a, unsigned long long b) {
    asm("fma.rn.f32x2 %0, %1, %2, %0;" : "+l"(d) : "l"(a), "l"(b));
}
__device__ __forceinline__ float2 unpack2(unsigned long long v) {
    float2 f;
    asm("mov.b64 {%0, %1}, %2;" : "=f"(f.x), "=f"(f.y) : "l"(v));
    return f;
}

// ---------------------------------------------------------------------------
// Kernel 0: zero CSR counters + normalize pos_enc
// grid = 64 (zero cnt) + 32 (pos_enc), block = 256
// ---------------------------------------------------------------------------
__global__ void __launch_bounds__(256) prep_kernel(const float* __restrict__ pos_enc)
{
    int b = blockIdx.x;
    int tid = threadIdx.x;
    if (b < 64) {
        ((int4*)g_cnt)[b * 256 + tid] = make_int4(0, 0, 0, 0);
    } else {
        int t2 = (b - 64) * 256 + tid;          // one thread per (kvol, h, d)
        if (t2 < KVOL * NHEAD * HD) {
            float v = pos_enc[t2];
            float ss = v * v;
            ss += __shfl_xor_sync(0xffffffffu, ss, 1);
            ss += __shfl_xor_sync(0xffffffffu, ss, 2);
            ss += __shfl_xor_sync(0xffffffffu, ss, 4);
            ss += __shfl_xor_sync(0xffffffffu, ss, 8);
            float n = sqrtf(ss);
            g_npos[t2] = v / fmaxf(n, 1e-12f);
        }
    }
}

// ---------------------------------------------------------------------------
// CSR build: histogram by out_idx
// ---------------------------------------------------------------------------
__global__ void __launch_bounds__(256) hist_kernel(const int* __restrict__ kq)
{
    int p = blockIdx.x * 256 + threadIdx.x;
    atomicAdd(&g_cnt[kq[NPAIR + p]], 1);
}

// block-local exclusive scan (256 blocks x 256 elements)
__global__ void __launch_bounds__(256) scan_part_kernel()
{
    __shared__ int s[256];
    int tid = threadIdx.x;
    int idx = blockIdx.x * 256 + tid;
    int v = g_cnt[idx];
    s[tid] = v;
    __syncthreads();
    #pragma unroll
    for (int d = 1; d < 256; d <<= 1) {
        int t = (tid >= d) ? s[tid - d] : 0;
        __syncthreads();
        s[tid] += t;
        __syncthreads();
    }
    g_off[idx] = s[tid] - v;                 // exclusive within block
    if (tid == 255) g_bsum[blockIdx.x] = s[tid];
}

// exclusive scan of the 256 block sums (single block)
__global__ void __launch_bounds__(256) scan_block_kernel()
{
    __shared__ int s[256];
    int tid = threadIdx.x;
    int v = g_bsum[tid];
    s[tid] = v;
    __syncthreads();
    #pragma unroll
    for (int d = 1; d < 256; d <<= 1) {
        int t = (tid >= d) ? s[tid - d] : 0;
        __syncthreads();
        s[tid] += t;
        __syncthreads();
    }
    g_bsum[tid] = s[tid] - v;                // exclusive
}

// add block prefixes -> global exclusive offsets; reset cnt for rank reuse
__global__ void __launch_bounds__(256) scan_add_kernel()
{
    int idx = blockIdx.x * 256 + threadIdx.x;
    g_off[idx] += g_bsum[blockIdx.x];
    g_cnt[idx] = 0;
    if (idx == 0) g_off[NVOX] = NPAIR;
}

// scatter packed i0 into CSR order
__global__ void __launch_bounds__(256) fill_kernel(const int* __restrict__ kq)
{
    int p = blockIdx.x * 256 + threadIdx.x;
    int o = kq[NPAIR + p];
    int r = atomicAdd(&g_cnt[o], 1);
    g_pi0[g_off[o] + r] = (unsigned)kq[p];
}

// ---------------------------------------------------------------------------
// Kernel: fused QKV projection + per-head L2 normalize (q,k only)
// grid=(1024,3), block=256 (16x16), thread computes 4 rows x 4 cols.
// Inner loop: f32x2 packed FMAs, xs read as float4 along k.
// ---------------------------------------------------------------------------
__global__ void __launch_bounds__(256) qkv_kernel(
    const float* __restrict__ x,
    const float* __restrict__ Wq, const float* __restrict__ bq,
    const float* __restrict__ Wk, const float* __restrict__ bk,
    const float* __restrict__ Wv, const float* __restrict__ bv)
{
    __shared__ __align__(16) float Ws[64 * 64];
    __shared__ __align__(16) float xs[64 * 68];   // row-major, stride 68 (16B-aligned, conflict-free)

    const int m = blockIdx.y;
    const float* __restrict__ W    = (m == 0) ? Wq : (m == 1) ? Wk : Wv;
    const float* __restrict__ bias = (m == 0) ? bq : (m == 1) ? bk : bv;
    float* __restrict__ outp       = (m == 0) ? g_nq : (m == 1) ? g_nk : g_v;

    const int rbase = blockIdx.x * 64;
    const int tid = threadIdx.x;

    #pragma unroll
    for (int i = 0; i < 4; i++)
        ((float4*)Ws)[tid + i * 256] = ((const float4*)W)[tid + i * 256];
    #pragma unroll
    for (int i = 0; i < 4; i++) {
        int idx = tid + i * 256;          // float4 index in [0,1024)
        int row = idx >> 4, c4 = idx & 15;
        float4 t = ((const float4*)x)[(unsigned)(rbase + row) * 16 + c4];
        *(float4*)&xs[row * 68 + c4 * 4] = t;
    }
    __syncthreads();

    const int tc = tid & 15;     // channels tc*4 .. tc*4+3
    const int tr = tid >> 4;     // rows     tr*4 .. tr*4+3

    unsigned long long acc[4][2] = {};   // [row][col-pair], each holds 2 fp32

    #pragma unroll
    for (int k4 = 0; k4 < 16; k4++) {
        float4 a0 = *(const float4*)&xs[(tr * 4 + 0) * 68 + k4 * 4];
        float4 a1 = *(const float4*)&xs[(tr * 4 + 1) * 68 + k4 * 4];
        float4 a2 = *(const float4*)&xs[(tr * 4 + 2) * 68 + k4 * 4];
        float4 a3 = *(const float4*)&xs[(tr * 4 + 3) * 68 + k4 * 4];
        const float* pa0 = (const float*)&a0;
        const float* pa1 = (const float*)&a1;
        const float* pa2 = (const float*)&a2;
        const float* pa3 = (const float*)&a3;
        #pragma unroll
        for (int kk = 0; kk < 4; kk++) {
            ulonglong2 w = *(const ulonglong2*)&Ws[(k4 * 4 + kk) * 64 + tc * 4];
            unsigned long long p0 = pack2(pa0[kk]);
            unsigned long long p1 = pack2(pa1[kk]);
            unsigned long long p2 = pack2(pa2[kk]);
            unsigned long long p3 = pack2(pa3[kk]);
            fma2(acc[0][0], p0, w.x); fma2(acc[0][1], p0, w.y);
            fma2(acc[1][0], p1, w.x); fma2(acc[1][1], p1, w.y);
            fma2(acc[2][0], p2, w.x); fma2(acc[2][1], p2, w.y);
            fma2(acc[3][0], p3, w.x); fma2(acc[3][1], p3, w.y);
        }
    }

    float4 bvec = *(const float4*)&bias[tc * 4];
    #pragma unroll
    for (int j = 0; j < 4; j++) {
        float2 c01 = unpack2(acc[j][0]);
        float2 c23 = unpack2(acc[j][1]);
        float v0 = c01.x + bvec.x;
        float v1 = c01.y + bvec.y;
        float v2 = c23.x + bvec.z;
        float v3 = c23.y + bvec.w;
        if (m != 2) {
            float ss = v0 * v0 + v1 * v1 + v2 * v2 + v3 * v3;
            ss += __shfl_xor_sync(0xffffffffu, ss, 1);
            ss += __shfl_xor_sync(0xffffffffu, ss, 2);
            float scale = 1.0f / fmaxf(sqrtf(ss), 1e-12f);
            v0 *= scale; v1 *= scale; v2 *= scale; v3 *= scale;
        }
        int row = rbase + tr * 4 + j;
        *(float4*)&outp[(unsigned)row * 64 + tc * 4] = make_float4(v0, v1, v2, v3);
    }
}

// ---------------------------------------------------------------------------
// Kernel: CSR gather attention. One warp per query voxel, float2 per lane.
// No atomics: register accumulation + one coalesced 256B store per voxel.
// ---------------------------------------------------------------------------
__global__ void __launch_bounds__(256) gather_kernel()
{
    const int o    = (blockIdx.x * 256 + threadIdx.x) >> 5;
    const int lane = threadIdx.x & 31;

    const float2 q = *(const float2*)&g_nq[(unsigned)o * 64 + lane * 2];
    int j = g_off[o];
    const int end = g_off[o + 1];

    float ax = 0.f, ay = 0.f;
    unsigned i0 = (j < end) ? g_pi0[j] : 0u;
    while (j < end) {
        unsigned nxt = (j + 1 < end) ? g_pi0[j + 1] : 0u;   // prefetch
        unsigned in  = i0 / 125u;
        unsigned kid = i0 - in * 125u;
        float2 k2 = *(const float2*)&g_nk  [in  * 64u + lane * 2];
        float2 p2 = *(const float2*)&g_npos[kid * 64u + lane * 2];
        float2 v2 = *(const float2*)&g_v   [in  * 64u + lane * 2];
        float s = q.x * (k2.x + p2.x) + q.y * (k2.y + p2.y);
        // reduce over the 8 lanes of this head (16 channels / 2 per lane)
        s += __shfl_xor_sync(0xffffffffu, s, 1);
        s += __shfl_xor_sync(0xffffffffu, s, 2);
        s += __shfl_xor_sync(0xffffffffu, s, 4);
        ax = fmaf(s, v2.x, ax);
        ay = fmaf(s, v2.y, ay);
        i0 = nxt;
        ++j;
    }
    *(float2*)&g_agg[(unsigned)o * 64 + lane * 2] = make_float2(ax, ay);
}

// ---------------------------------------------------------------------------
// Kernel: output projection + bias + residual (same tiling as qkv)
// ---------------------------------------------------------------------------
__global__ void __launch_bounds__(256) out_kernel(
    const float* __restrict__ Wo, const float* __restrict__ bo,
    const float* __restrict__ x, float* __restrict__ out)
{
    __shared__ __align__(16) float Ws[64 * 64];
    __shared__ __align__(16) float xs[64 * 68];

    const int rbase = blockIdx.x * 64;
    const int tid = threadIdx.x;

    #pragma unroll
    for (int i = 0; i < 4; i++)
        ((float4*)Ws)[tid + i * 256] = ((const float4*)Wo)[tid + i * 256];
    #pragma unroll
    for (int i = 0; i < 4; i++) {
        int idx = tid + i * 256;
        int row = idx >> 4, c4 = idx & 15;
        float4 t = ((const float4*)g_agg)[(unsigned)(rbase + row) * 16 + c4];
        *(float4*)&xs[row * 68 + c4 * 4] = t;
    }
    __syncthreads();

    const int tc = tid & 15;
    const int tr = tid >> 4;

    unsigned long long acc[4][2] = {};

    #pragma unroll
    for (int k4 = 0; k4 < 16; k4++) {
        float4 a0 = *(const float4*)&xs[(tr * 4 + 0) * 68 + k4 * 4];
        float4 a1 = *(const float4*)&xs[(tr * 4 + 1) * 68 + k4 * 4];
        float4 a2 = *(const float4*)&xs[(tr * 4 + 2) * 68 + k4 * 4];
        float4 a3 = *(const float4*)&xs[(tr * 4 + 3) * 68 + k4 * 4];
        const float* pa0 = (const float*)&a0;
        const float* pa1 = (const float*)&a1;
        const float* pa2 = (const float*)&a2;
        const float* pa3 = (const float*)&a3;
        #pragma unroll
        for (int kk = 0; kk < 4; kk++) {
            ulonglong2 w = *(const ulonglong2*)&Ws[(k4 * 4 + kk) * 64 + tc * 4];
            unsigned long long p0 = pack2(pa0[kk]);
            unsigned long long p1 = pack2(pa1[kk]);
            unsigned long long p2 = pack2(pa2[kk]);
            unsigned long long p3 = pack2(pa3[kk]);
            fma2(acc[0][0], p0, w.x); fma2(acc[0][1], p0, w.y);
            fma2(acc[1][0], p1, w.x); fma2(acc[1][1], p1, w.y);
            fma2(acc[2][0], p2, w.x); fma2(acc[2][1], p2, w.y);
            fma2(acc[3][0], p3, w.x); fma2(acc[3][1], p3, w.y);
        }
    }

    float4 bvec = *(const float4*)&bo[tc * 4];
    #pragma unroll
    for (int j = 0; j < 4; j++) {
        int row = rbase + tr * 4 + j;
        float4 res = *(const float4*)&x[(unsigned)row * 64 + tc * 4];
        float2 c01 = unpack2(acc[j][0]);
        float2 c23 = unpack2(acc[j][1]);
        float4 ov;
        ov.x = c01.x + bvec.x + res.x;
        ov.y = c01.y + bvec.y + res.y;
        ov.z = c23.x + bvec.z + res.z;
        ov.w = c23.y + bvec.w + res.w;
        *(float4*)&out[(unsigned)row * 64 + tc * 4] = ov;
    }
}

// ---------------------------------------------------------------------------
// Launch. Input order (metadata): x, Wq, bq, Wk, bk, Wv, bv, Wo, bo,
//                                 pos_enc, kq_map
// ---------------------------------------------------------------------------
extern "C" void kernel_launch(void* const* d_in, const int* in_sizes, int n_in,
                              void* d_out, int out_size)
{
    const float* x       = (const float*)d_in[0];
    const float* Wq      = (const float*)d_in[1];
    const float* bq      = (const float*)d_in[2];
    const float* Wk      = (const float*)d_in[3];
    const float* bk      = (const float*)d_in[4];
    const float* Wv      = (const float*)d_in[5];
    const float* bv      = (const float*)d_in[6];
    const float* Wo      = (const float*)d_in[7];
    const float* bo      = (const float*)d_in[8];
    const float* pos_enc = (const float*)d_in[9];
    const int*   kq      = (const int*)d_in[10];
    float* out = (float*)d_out;

    prep_kernel<<<64 + 32, 256>>>(pos_enc);
    hist_kernel<<<NPAIR / 256, 256>>>(kq);
    scan_part_kernel<<<256, 256>>>();
    scan_block_kernel<<<1, 256>>>();
    scan_add_kernel<<<256, 256>>>();
    fill_kernel<<<NPAIR / 256, 256>>>(kq);
    qkv_kernel<<<dim3(NVOX / 64, 3), 256>>>(x, Wq, bq, Wk, bk, Wv, bv);
    gather_kernel<<<NVOX * 32 / 256, 256>>>();
    out_kernel<<<NVOX / 64, 256>>>(Wo, bo, x, out);
}